// round 16
// baseline (speedup 1.0000x reference)
#include <cuda_runtime.h>
#include <cuda_fp16.h>
#include <math_constants.h>

// Problem sizes (fixed by the dataset): B=4, N=20000, E=640000, H=8
#define MAXB 4
#define MAXN 20000
#define MAXE 640000
#define BNB   (MAXB * MAXN)
#define BEMAX (MAXB * MAXE)
#define CAP   160                         // padded CSR bucket capacity per node

// Scratch (device globals; no dynamic allocation allowed)
__device__ float g_pdA[BNB * 8];          // dst-role node projections (fp32)
__device__ float g_pdB[BNB * 8];
__device__ __align__(16) __half2 g_psA[BNB * 4];   // src-role projections, fp16x8 = 16B/node
__device__ __align__(16) __half2 g_psB[BNB * 4];
__device__ int   g_deg [BNB];             // per-node in-degree
__device__ int2  g_csr [BNB * CAP];       // padded CSR: (src, ea-bits)
__device__ float g_pool[MAXB * 11];       // per-graph pooled sums

__device__ __forceinline__ float lrelu(float x) { return fmaxf(x, 0.01f * x); }

// unpack 8 halves (as int4) -> 8 floats
#define UNPACK8(dst, raw) do {                                                 \
    float2 _f;                                                                 \
    _f = __half22float2(*(const __half2*)&(raw).x); dst[0]=_f.x; dst[1]=_f.y;  \
    _f = __half22float2(*(const __half2*)&(raw).y); dst[2]=_f.x; dst[3]=_f.y;  \
    _f = __half22float2(*(const __half2*)&(raw).z); dst[4]=_f.x; dst[5]=_f.y;  \
    _f = __half22float2(*(const __half2*)&(raw).w); dst[6]=_f.x; dst[7]=_f.y;  \
} while (0)

// ---------------------------------------------------------------------------
// K-1: zero pooled sums BEFORE any kernel accumulates into them
// ---------------------------------------------------------------------------
__global__ void k_zero() {
    int t = threadIdx.x;
    if (t < MAXB * 11) g_pool[t] = 0.0f;
}

// ---------------------------------------------------------------------------
// K0: layer-1 node projections (input dim 3), zero deg, pool x0 sums
// ---------------------------------------------------------------------------
__global__ void k_prep(const int* __restrict__ nf, const float* __restrict__ act,
                       const float* __restrict__ W1, int BN, int N) {
    __shared__ float s[2][3];            // block straddles at most 2 graphs
    int t = threadIdx.x;
    if (t < 6) ((float*)s)[t] = 0.0f;
    __syncthreads();

    int i  = blockIdx.x * blockDim.x + t;
    int b0 = (blockIdx.x * blockDim.x) / N;
    if (i < BN) {
        g_deg[i] = 0;
        float x0 = (float)nf[2 * i];
        float x1 = (float)nf[2 * i + 1];
        float x2 = act[i];
        float psv[8];
#pragma unroll
        for (int j = 0; j < 8; j++) {
            // W1 rows 0..2 -> dst part, rows 3..5 -> src part (row 6 = edge attr)
            g_pdA[8 * i + j] = fmaf(x0, __ldg(W1 + 0 * 8 + j),
                               fmaf(x1, __ldg(W1 + 1 * 8 + j),
                                    x2 * __ldg(W1 + 2 * 8 + j)));
            psv[j] = fmaf(x0, __ldg(W1 + 3 * 8 + j),
                     fmaf(x1, __ldg(W1 + 4 * 8 + j),
                          x2 * __ldg(W1 + 5 * 8 + j)));
        }
        uint4 pk;
        __half2 hh;
        hh = __floats2half2_rn(psv[0], psv[1]); pk.x = *(unsigned int*)&hh;
        hh = __floats2half2_rn(psv[2], psv[3]); pk.y = *(unsigned int*)&hh;
        hh = __floats2half2_rn(psv[4], psv[5]); pk.z = *(unsigned int*)&hh;
        hh = __floats2half2_rn(psv[6], psv[7]); pk.w = *(unsigned int*)&hh;
        *(uint4*)(g_psA + 4 * i) = pk;

        int slot = i / N - b0;
        atomicAdd(&s[slot][0], x0);
        atomicAdd(&s[slot][1], x1);
        atomicAdd(&s[slot][2], x2);
    }
    __syncthreads();
    if (t < 6) {
        int slot = t / 3, cc = t - slot * 3;
        int b = b0 + slot;
        if (b < BN / N) atomicAdd(&g_pool[b * 11 + cc], s[slot][cc]);
    }
}

// ---------------------------------------------------------------------------
// K1: fused histogram + scatter. The atomicAdd return value IS this edge's
// rank in its dst bucket: pos = dst*CAP + rank. One pass, no scan, no rank
// array. Slot order within a node is irrelevant (exact-float min commutes).
// ---------------------------------------------------------------------------
__global__ void k_build(const int* __restrict__ ei, const float* __restrict__ ea,
                        int B, int E, int N) {
    int e = blockIdx.x * blockDim.x + threadIdx.x;
    if (e >= B * E) return;
    int b = e / E;
    int k = e - b * E;
    int s = ei[b * 2 * E + k]     + b * N;
    int d = ei[b * 2 * E + E + k] + b * N;
    int r = atomicAdd(&g_deg[d], 1);
    if (r < CAP) g_csr[d * CAP + r] = make_int2(s, __float_as_int(ea[e]));
}

// ---------------------------------------------------------------------------
// K2 (x3): 16-lanes-per-node gather, 2-edge batched (avg deg 32 -> ONE trip
// through the csr->ps chain: both csr loads then both 16B ps loads issued
// back-to-back). ps is fp16x8 (one LDG.128/edge — half the wavefronts of the
// fp32 version). Full 8x8 GEMV per lane in fp32; no shuffles in the loop;
// 4-step butterfly min at the end. b2 folded out of the min; pd[dst]+b1
// hoisted per node. phase: 0 = read A write B, 1 = read B write A.
// last: pool h sums. Grid exact (BN*16 threads), blocks never straddle the
// l16 grouping.
// ---------------------------------------------------------------------------
__global__ void __launch_bounds__(256, 2)
k_gather(const float* __restrict__ crow,
         const float* __restrict__ b1,
         const float* __restrict__ W2,
         const float* __restrict__ b2,
         const float* __restrict__ W1n,
         int phase, int last, int BN, int N) {
    __shared__ float spool[2][8];
    int t = threadIdx.x;
    if (last && t < 16) ((float*)spool)[t] = 0.0f;
    if (last) __syncthreads();

    int node = (blockIdx.x * blockDim.x + t) >> 4;   // 16 lanes per node
    int l16  = t & 15;

    const __half2* ps_in  = phase ? g_psB : g_psA;
    const float*   pd_in  = phase ? g_pdB : g_pdA;
    float*         pd_out = phase ? g_pdA : g_pdB;
    __half2*       ps_out = phase ? g_psA : g_psB;

    float c[8], pdb[8], w2[64];
#pragma unroll
    for (int j = 0; j < 8; j++) {
        c[j]   = __ldg(crow + j);
        pdb[j] = pd_in[8 * node + j] + __ldg(b1 + j);
    }
#pragma unroll
    for (int j = 0; j < 64; j++) w2[j] = __ldg(W2 + j);

    int deg   = min(__ldg(&g_deg[node]), CAP);
    long base = (long)node * CAP;

    float acc[8];
#pragma unroll
    for (int j = 0; j < 8; j++) acc[j] = CUDART_INF_F;

    for (int i = l16; i < deg; i += 32) {
        bool has2 = (i + 16) < deg;
        int2 pr0 = __ldg(&g_csr[base + i]);
        int2 pr1 = has2 ? __ldg(&g_csr[base + i + 16]) : pr0;

        // both 16B gathers in flight before any arithmetic
        int4 raw0 = __ldg((const int4*)(ps_in + 4 * pr0.x));
        int4 raw1 = __ldg((const int4*)(ps_in + 4 * pr1.x));

        float ea0 = __int_as_float(pr0.y);
        float ea1 = __int_as_float(pr1.y);
        float ps0[8], ps1[8];
        UNPACK8(ps0, raw0);
        UNPACK8(ps1, raw1);

        float h0[8], h1[8];
#pragma unroll
        for (int k = 0; k < 8; k++) {
            h0[k] = lrelu(fmaf(c[k], ea0, pdb[k] + ps0[k]));
            h1[k] = lrelu(fmaf(c[k], ea1, pdb[k] + ps1[k]));
        }

#pragma unroll
        for (int j = 0; j < 8; j++) {
            float o0 = h0[0] * w2[0 * 8 + j];
            float o1 = h1[0] * w2[0 * 8 + j];
#pragma unroll
            for (int k = 1; k < 8; k++) {
                o0 = fmaf(h0[k], w2[k * 8 + j], o0);
                o1 = fmaf(h1[k], w2[k * 8 + j], o1);
            }
            acc[j] = fminf(acc[j], o0);
            if (has2) acc[j] = fminf(acc[j], o1);
        }
    }

    // butterfly min over the 16-lane group (xor 8,4,2,1 stay in-group)
#pragma unroll
    for (int off = 8; off > 0; off >>= 1)
#pragma unroll
        for (int j = 0; j < 8; j++)
            acc[j] = fminf(acc[j], __shfl_xor_sync(0xffffffffu, acc[j], off));

    float h[8];
#pragma unroll
    for (int j = 0; j < 8; j++) {
        // empty node -> 0, else add back b2; then outer LeakyReLU
        float v = (__float_as_uint(acc[j]) == 0x7f800000u)
                      ? 0.0f : (acc[j] + __ldg(b2 + j));
        h[j] = lrelu(v);
    }

    if (!last) {
        float a = 0.0f, bb = 0.0f;
        if (l16 < 8) {
            // lane j computes next-layer projection column j
#pragma unroll
            for (int k = 0; k < 8; k++) {
                a  = fmaf(h[k], __ldg(W1n + k * 8 + l16), a);
                bb = fmaf(h[k], __ldg(W1n + (8 + k) * 8 + l16), bb);
            }
            pd_out[8 * node + l16] = a;
        }
        // pack ps pairs: even lane j writes half2(channel j, channel j+1)
        float bbn = __shfl_xor_sync(0xffffffffu, bb, 1);
        if (l16 < 8 && !(l16 & 1))
            ps_out[4 * node + (l16 >> 1)] = __floats2half2_rn(bb, bbn);
    } else {
        // pool h sums per graph: lane l16<8 contributes channel l16 of this
        // node exactly once (each lane owns a distinct channel).
        int node0 = blockIdx.x * (blockDim.x >> 4);
        int b0 = node0 / N;
        if (l16 < 8) {
            int slot = node / N - b0;
            atomicAdd(&spool[slot][l16], h[l16]);
        }
        __syncthreads();
        if (t < 16) {
            int slot2 = t >> 3, j = t & 7;
            int b = b0 + slot2;
            if (b < BN / N) atomicAdd(&g_pool[b * 11 + 3 + j], spool[slot2][j]);
        }
    }
}

// ---------------------------------------------------------------------------
// K3: final linear  out[b] = pool[b] . lin_W + lin_b
// ---------------------------------------------------------------------------
__global__ void k_out(const float* __restrict__ linW, const float* __restrict__ linb,
                      float* __restrict__ out, int B) {
    int b = threadIdx.x;
    if (b < B) {
        float acc = __ldg(linb);
#pragma unroll
        for (int k = 0; k < 11; k++) acc = fmaf(g_pool[b * 11 + k], __ldg(linW + k), acc);
        out[b] = acc;
    }
}

extern "C" void kernel_launch(void* const* d_in, const int* in_sizes, int n_in,
                              void* d_out, int out_size) {
    const int*   nf   = (const int*)d_in[0];
    const float* act  = (const float*)d_in[1];
    const int*   ei   = (const int*)d_in[2];   // int32 (JAX x64 disabled)
    const float* ea   = (const float*)d_in[3];
    const float* c1W1 = (const float*)d_in[4];
    const float* c1b1 = (const float*)d_in[5];
    const float* c1W2 = (const float*)d_in[6];
    const float* c1b2 = (const float*)d_in[7];
    const float* c2W1 = (const float*)d_in[8];
    const float* c2b1 = (const float*)d_in[9];
    const float* c2W2 = (const float*)d_in[10];
    const float* c2b2 = (const float*)d_in[11];
    const float* c3W1 = (const float*)d_in[12];
    const float* c3b1 = (const float*)d_in[13];
    const float* c3W2 = (const float*)d_in[14];
    const float* c3b2 = (const float*)d_in[15];
    const float* linW = (const float*)d_in[16];
    const float* linb = (const float*)d_in[17];

    int B  = out_size;         // 4
    int BN = in_sizes[1];      // B*N = 80000
    int N  = BN / B;           // 20000
    int BE = in_sizes[3];      // B*E = 2560000
    int E  = BE / B;           // 640000

    int nb_node   = (BN + 255) / 256;        // 313
    int nb_edge   = (BE + 255) / 256;
    int nb_gather = (BN * 16) / 256;         // 16 lanes per node: 5000 blocks

    k_zero <<<1, 64>>>();
    k_prep <<<nb_node, 256>>>(nf, act, c1W1, BN, N);
    k_build<<<nb_edge, 256>>>(ei, ea, B, E, N);

    // layer 1 (input dim 3: edge-attr row = W1[6]); read A, write B
    k_gather<<<nb_gather, 256>>>(c1W1 + 6 * 8,  c1b1, c1W2, c1b2, c2W1, 0, 0, BN, N);
    // layer 2 (input dim 8: edge-attr row = W1[16]); read B, write A
    k_gather<<<nb_gather, 256>>>(c2W1 + 16 * 8, c2b1, c2W2, c2b2, c3W1, 1, 0, BN, N);
    // layer 3; read A, pool h directly
    k_gather<<<nb_gather, 256>>>(c3W1 + 16 * 8, c3b1, c3W2, c3b2, c3W1, 0, 1, BN, N);

    k_out<<<1, 32>>>(linW, linb, (float*)d_out, B);
}

// round 17
// speedup vs baseline: 1.3311x; 1.3311x over previous
#include <cuda_runtime.h>
#include <math_constants.h>

// Problem sizes (fixed by the dataset): B=4, N=20000, E=640000, H=8
#define MAXB 4
#define MAXN 20000
#define MAXE 640000
#define BNB   (MAXB * MAXN)
#define BEMAX (MAXB * MAXE)
#define CAP   160                         // padded CSR bucket capacity per node

// Scratch (device globals; no dynamic allocation allowed)
__device__ float g_pdA[BNB * 8];          // node projections, buffer A (dst role)
__device__ float g_psA[BNB * 8];          //                            (src role)
__device__ float g_pdB[BNB * 8];          // buffer B
__device__ float g_psB[BNB * 8];
__device__ int   g_deg [BNB];             // per-node in-degree
__device__ int2  g_csr [BNB * CAP];       // padded CSR: (src, ea-bits)
__device__ float g_pool[MAXB * 11];       // per-graph pooled sums

__device__ __forceinline__ float lrelu(float x) { return fmaxf(x, 0.01f * x); }

// ---------------------------------------------------------------------------
// K-1: zero pooled sums BEFORE any kernel accumulates into them
// ---------------------------------------------------------------------------
__global__ void k_zero() {
    int t = threadIdx.x;
    if (t < MAXB * 11) g_pool[t] = 0.0f;
}

// ---------------------------------------------------------------------------
// K0: layer-1 node projections (input dim 3), zero deg, pool x0 sums
// ---------------------------------------------------------------------------
__global__ void k_prep(const int* __restrict__ nf, const float* __restrict__ act,
                       const float* __restrict__ W1, int BN, int N) {
    __shared__ float s[2][3];            // block straddles at most 2 graphs
    int t = threadIdx.x;
    if (t < 6) ((float*)s)[t] = 0.0f;
    __syncthreads();

    int i  = blockIdx.x * blockDim.x + t;
    int b0 = (blockIdx.x * blockDim.x) / N;
    if (i < BN) {
        g_deg[i] = 0;
        float x0 = (float)nf[2 * i];
        float x1 = (float)nf[2 * i + 1];
        float x2 = act[i];
#pragma unroll
        for (int j = 0; j < 8; j++) {
            // W1 rows 0..2 -> dst part, rows 3..5 -> src part (row 6 = edge attr)
            g_pdA[8 * i + j] = fmaf(x0, __ldg(W1 + 0 * 8 + j),
                               fmaf(x1, __ldg(W1 + 1 * 8 + j),
                                    x2 * __ldg(W1 + 2 * 8 + j)));
            g_psA[8 * i + j] = fmaf(x0, __ldg(W1 + 3 * 8 + j),
                               fmaf(x1, __ldg(W1 + 4 * 8 + j),
                                    x2 * __ldg(W1 + 5 * 8 + j)));
        }
        int slot = i / N - b0;
        atomicAdd(&s[slot][0], x0);
        atomicAdd(&s[slot][1], x1);
        atomicAdd(&s[slot][2], x2);
    }
    __syncthreads();
    if (t < 6) {
        int slot = t / 3, cc = t - slot * 3;
        int b = b0 + slot;
        if (b < BN / N) atomicAdd(&g_pool[b * 11 + cc], s[slot][cc]);
    }
}

// ---------------------------------------------------------------------------
// K1: fused histogram + scatter. The atomicAdd return value IS this edge's
// rank in its dst bucket: pos = dst*CAP + rank. One pass, no scan, no rank
// array. Slot order within a node is irrelevant (exact-float min commutes).
// ---------------------------------------------------------------------------
__global__ void k_build(const int* __restrict__ ei, const float* __restrict__ ea,
                        int B, int E, int N) {
    int e = blockIdx.x * blockDim.x + threadIdx.x;
    if (e >= B * E) return;
    int b = e / E;
    int k = e - b * E;
    int s = ei[b * 2 * E + k]     + b * N;
    int d = ei[b * 2 * E + E + k] + b * N;
    int r = atomicAdd(&g_deg[d], 1);
    if (r < CAP) g_csr[d * CAP + r] = make_int2(s, __float_as_int(ea[e]));
}

// ---------------------------------------------------------------------------
// K2 (x3): 8-lanes-per-node gather (4 nodes/warp, 128 edges/warp so the
// prologue is amortized). Measured-best shape (R14). Two fixes vs R14:
//  (a) vectorized prologue — w2 via 16x LDG.128, c/b1/pd/b2 via float4
//      (~80 scalar LDGs -> ~26 vector LDGs, all independent);
//  (b) software-pipelined csr prefetch — next trip's csr entry is in
//      flight while this trip's ps gathers + math run.
// launch_bounds(256,2): 2 blocks/SM. No shuffles in the loop; 3-step
// butterfly min at the end. b2 folded out of the min; pd[dst]+b1 hoisted.
// phase: 0 = read A write B, 1 = read B write A. last: pool h sums.
// ---------------------------------------------------------------------------
__global__ void __launch_bounds__(256, 2)
k_gather(const float* __restrict__ crow,
         const float* __restrict__ b1,
         const float* __restrict__ W2,
         const float* __restrict__ b2,
         const float* __restrict__ W1n,
         int phase, int last, int BN, int N) {
    __shared__ float spool[2][8];
    int t = threadIdx.x;
    if (last && t < 16) ((float*)spool)[t] = 0.0f;
    if (last) __syncthreads();

    int node = (blockIdx.x * blockDim.x + t) >> 3;   // 8 lanes per node
    int l8   = t & 7;

    const float* ps_in  = phase ? g_psB : g_psA;
    const float* pd_in  = phase ? g_pdB : g_pdA;
    float*       pd_out = phase ? g_pdA : g_pdB;
    float*       ps_out = phase ? g_psA : g_psB;

    // Vectorized prologue (all loads independent 128-bit)
    float w2[64], c[8], pdb[8];
#pragma unroll
    for (int j = 0; j < 16; j++)
        *(float4*)&w2[4 * j] = __ldg((const float4*)W2 + j);
    {
        float4 c0 = __ldg((const float4*)crow);
        float4 c1 = __ldg((const float4*)crow + 1);
        float4 bb0 = __ldg((const float4*)b1);
        float4 bb1 = __ldg((const float4*)b1 + 1);
        float4 p0 = *(const float4*)(pd_in + 8 * node);
        float4 p1 = *(const float4*)(pd_in + 8 * node + 4);
        c[0]=c0.x; c[1]=c0.y; c[2]=c0.z; c[3]=c0.w;
        c[4]=c1.x; c[5]=c1.y; c[6]=c1.z; c[7]=c1.w;
        pdb[0]=p0.x+bb0.x; pdb[1]=p0.y+bb0.y; pdb[2]=p0.z+bb0.z; pdb[3]=p0.w+bb0.w;
        pdb[4]=p1.x+bb1.x; pdb[5]=p1.y+bb1.y; pdb[6]=p1.z+bb1.z; pdb[7]=p1.w+bb1.w;
    }

    int deg   = min(__ldg(&g_deg[node]), CAP);
    long base = (long)node * CAP;

    float acc[8];
#pragma unroll
    for (int j = 0; j < 8; j++) acc[j] = CUDART_INF_F;

    // software-pipelined loop: csr entry for trip i+1 issued before trip i's
    // ps gathers + compute
    int i = l8;
    int2 pr = (i < deg) ? __ldg(&g_csr[base + i]) : make_int2(0, 0);
    while (i < deg) {
        int inext = i + 8;
        int2 prn = (inext < deg) ? __ldg(&g_csr[base + inext]) : pr;

        float eav = __int_as_float(pr.y);
        float4 p0 = *(const float4*)(ps_in + 8 * pr.x);
        float4 p1 = *(const float4*)(ps_in + 8 * pr.x + 4);
        float psv[8] = {p0.x, p0.y, p0.z, p0.w, p1.x, p1.y, p1.z, p1.w};

        float hid[8];
#pragma unroll
        for (int k = 0; k < 8; k++)
            hid[k] = lrelu(fmaf(c[k], eav, pdb[k] + psv[k]));

#pragma unroll
        for (int j = 0; j < 8; j++) {
            float o = hid[0] * w2[0 * 8 + j];
#pragma unroll
            for (int k = 1; k < 8; k++) o = fmaf(hid[k], w2[k * 8 + j], o);
            acc[j] = fminf(acc[j], o);
        }

        pr = prn;
        i = inext;
    }

    // butterfly min over the 8-lane group (xor 4,2,1 stay within the group)
#pragma unroll
    for (int off = 4; off > 0; off >>= 1)
#pragma unroll
        for (int j = 0; j < 8; j++)
            acc[j] = fminf(acc[j], __shfl_xor_sync(0xffffffffu, acc[j], off));

    float b2r[8];
    {
        float4 q0 = __ldg((const float4*)b2);
        float4 q1 = __ldg((const float4*)b2 + 1);
        b2r[0]=q0.x; b2r[1]=q0.y; b2r[2]=q0.z; b2r[3]=q0.w;
        b2r[4]=q1.x; b2r[5]=q1.y; b2r[6]=q1.z; b2r[7]=q1.w;
    }

    float h[8];
#pragma unroll
    for (int j = 0; j < 8; j++) {
        // empty node -> 0, else add back b2; then outer LeakyReLU
        float v = (__float_as_uint(acc[j]) == 0x7f800000u)
                      ? 0.0f : (acc[j] + b2r[j]);
        h[j] = lrelu(v);
    }

    if (!last) {
        // lane j computes next-layer projection column j
        float a = 0.0f, bb = 0.0f;
#pragma unroll
        for (int k = 0; k < 8; k++) {
            a  = fmaf(h[k], __ldg(W1n + k * 8 + l8), a);
            bb = fmaf(h[k], __ldg(W1n + (8 + k) * 8 + l8), bb);
        }
        pd_out[8 * node + l8] = a;
        ps_out[8 * node + l8] = bb;
    } else {
        // pool h sums per graph: lane l8 contributes channel l8 of this node
        // exactly once (each lane owns a distinct channel -> NO scaling).
        int node0 = blockIdx.x * (blockDim.x >> 3);
        int b0 = node0 / N;
        int slot = node / N - b0;
        atomicAdd(&spool[slot][l8], h[l8]);
        __syncthreads();
        if (t < 16) {
            int slot2 = t >> 3, j = t & 7;
            int b = b0 + slot2;
            if (b < BN / N) atomicAdd(&g_pool[b * 11 + 3 + j], spool[slot2][j]);
        }
    }
}

// ---------------------------------------------------------------------------
// K3: final linear  out[b] = pool[b] . lin_W + lin_b
// ---------------------------------------------------------------------------
__global__ void k_out(const float* __restrict__ linW, const float* __restrict__ linb,
                      float* __restrict__ out, int B) {
    int b = threadIdx.x;
    if (b < B) {
        float acc = __ldg(linb);
#pragma unroll
        for (int k = 0; k < 11; k++) acc = fmaf(g_pool[b * 11 + k], __ldg(linW + k), acc);
        out[b] = acc;
    }
}

extern "C" void kernel_launch(void* const* d_in, const int* in_sizes, int n_in,
                              void* d_out, int out_size) {
    const int*   nf   = (const int*)d_in[0];
    const float* act  = (const float*)d_in[1];
    const int*   ei   = (const int*)d_in[2];   // int32 (JAX x64 disabled)
    const float* ea   = (const float*)d_in[3];
    const float* c1W1 = (const float*)d_in[4];
    const float* c1b1 = (const float*)d_in[5];
    const float* c1W2 = (const float*)d_in[6];
    const float* c1b2 = (const float*)d_in[7];
    const float* c2W1 = (const float*)d_in[8];
    const float* c2b1 = (const float*)d_in[9];
    const float* c2W2 = (const float*)d_in[10];
    const float* c2b2 = (const float*)d_in[11];
    const float* c3W1 = (const float*)d_in[12];
    const float* c3b1 = (const float*)d_in[13];
    const float* c3W2 = (const float*)d_in[14];
    const float* c3b2 = (const float*)d_in[15];
    const float* linW = (const float*)d_in[16];
    const float* linb = (const float*)d_in[17];

    int B  = out_size;         // 4
    int BN = in_sizes[1];      // B*N = 80000
    int N  = BN / B;           // 20000
    int BE = in_sizes[3];      // B*E = 2560000
    int E  = BE / B;           // 640000

    int nb_node   = (BN + 255) / 256;        // 313
    int nb_edge   = (BE + 255) / 256;
    int nb_gather = (BN * 8) / 256;          // 8 lanes per node: 2500 blocks

    k_zero <<<1, 64>>>();
    k_prep <<<nb_node, 256>>>(nf, act, c1W1, BN, N);
    k_build<<<nb_edge, 256>>>(ei, ea, B, E, N);

    // layer 1 (input dim 3: edge-attr row = W1[6]); read A, write B
    k_gather<<<nb_gather, 256>>>(c1W1 + 6 * 8,  c1b1, c1W2, c1b2, c2W1, 0, 0, BN, N);
    // layer 2 (input dim 8: edge-attr row = W1[16]); read B, write A
    k_gather<<<nb_gather, 256>>>(c2W1 + 16 * 8, c2b1, c2W2, c2b2, c3W1, 1, 0, BN, N);
    // layer 3; read A, pool h directly
    k_gather<<<nb_gather, 256>>>(c3W1 + 16 * 8, c3b1, c3W2, c3b2, c3W1, 0, 1, BN, N);

    k_out<<<1, 32>>>(linW, linb, (float*)d_out, B);
}